// round 9
// baseline (speedup 1.0000x reference)
#include <cuda_runtime.h>
#include <cuda_fp16.h>
#include <cstdint>

#define B_SZ  2
#define HEADS 16
#define TKN   2048
#define DM    1024
#define DK    64

// ---- fp16 mma / ldmatrix / f16x2 helpers ----
__device__ __forceinline__ uint32_t cvta_s(const void* p) {
    return (uint32_t)__cvta_generic_to_shared(p);
}
__device__ __forceinline__ void ldm4(uint32_t* r, uint32_t a) {
    asm volatile("ldmatrix.sync.aligned.m8n8.x4.shared.b16 {%0,%1,%2,%3},[%4];"
        : "=r"(r[0]), "=r"(r[1]), "=r"(r[2]), "=r"(r[3]) : "r"(a));
}
__device__ __forceinline__ void ldm4t(uint32_t* r, uint32_t a) {
    asm volatile("ldmatrix.sync.aligned.m8n8.x4.trans.shared.b16 {%0,%1,%2,%3},[%4];"
        : "=r"(r[0]), "=r"(r[1]), "=r"(r[2]), "=r"(r[3]) : "r"(a));
}
__device__ __forceinline__ void mmah(float* d, uint32_t a0, uint32_t a1, uint32_t a2,
                                     uint32_t a3, uint32_t b0, uint32_t b1) {
    asm("mma.sync.aligned.m16n8k16.row.col.f32.f16.f16.f32 "
        "{%0,%1,%2,%3},{%4,%5,%6,%7},{%8,%9},{%0,%1,%2,%3};"
        : "+f"(d[0]), "+f"(d[1]), "+f"(d[2]), "+f"(d[3])
        : "r"(a0), "r"(a1), "r"(a2), "r"(a3), "r"(b0), "r"(b1));
}
__device__ __forceinline__ uint32_t cvt2h(float hi, float lo) {
    uint32_t d; asm("cvt.rn.f16x2.f32 %0, %1, %2;" : "=r"(d) : "f"(hi), "f"(lo)); return d;
}
__device__ __forceinline__ uint32_t ex2h2(uint32_t x) {
    uint32_t d; asm("ex2.approx.f16x2 %0, %1;" : "=r"(d) : "r"(x)); return d;
}
__device__ __forceinline__ float ex2f(float x) {
    float d; asm("ex2.approx.ftz.f32 %0, %1;" : "=f"(d) : "f"(x)); return d;
}
__device__ __forceinline__ uint32_t hadd2u(uint32_t a, uint32_t b) {
    uint32_t d; asm("add.rn.f16x2 %0, %1, %2;" : "=r"(d) : "r"(a), "r"(b)); return d;
}
__device__ __forceinline__ float h2sumf(uint32_t h) {
    __half2 v = *(__half2*)&h;
    return __low2float(v) + __high2float(v);
}
// cp.async 16B
__device__ __forceinline__ void cp16(uint32_t d, const void* s) {
    asm volatile("cp.async.ca.shared.global [%0], [%1], 16;" :: "r"(d), "l"(s));
}
__device__ __forceinline__ void cpcommit() {
    asm volatile("cp.async.commit_group;");
}
template <int N>
__device__ __forceinline__ void cpwait() {
    asm volatile("cp.async.wait_group %0;" :: "n"(N));
}

// ---- device-global scratch (no allocation) ----
__device__ __half g_Xf[3][B_SZ * TKN * DM];
__device__ __half g_Wf[3][HEADS * DM * DK];
__device__ __half g_Wof[DM * DM];
__device__ __half g_Qh[B_SZ * HEADS * TKN * DK]; // pre-scaled by 1/8
__device__ __half g_Kh[B_SZ * HEADS * TKN * DK];
__device__ __half g_Vh[B_SZ * HEADS * TKN * DK];
__device__ __half g_ctxh[B_SZ * HEADS * TKN * DK];

// ---------------------------------------------------------------------------
// Kernel 0: fused f32 -> f16 convert for all 7 tensors (blockIdx.y selects).
// ---------------------------------------------------------------------------
__global__ __launch_bounds__(256) void split_kernel(
    const float* __restrict__ Q, const float* __restrict__ K, const float* __restrict__ V,
    const float* __restrict__ Wq, const float* __restrict__ Wk, const float* __restrict__ Wv,
    const float* __restrict__ Wo)
{
    int y = blockIdx.y;
    const float* src; __half* dst; int n4;
    switch (y) {
        case 0: src = Q;  dst = g_Xf[0]; n4 = (B_SZ * TKN * DM) / 4; break;
        case 1: src = K;  dst = g_Xf[1]; n4 = (B_SZ * TKN * DM) / 4; break;
        case 2: src = V;  dst = g_Xf[2]; n4 = (B_SZ * TKN * DM) / 4; break;
        case 3: src = Wq; dst = g_Wf[0]; n4 = (HEADS * DM * DK) / 4; break;
        case 4: src = Wk; dst = g_Wf[1]; n4 = (HEADS * DM * DK) / 4; break;
        case 5: src = Wv; dst = g_Wf[2]; n4 = (HEADS * DM * DK) / 4; break;
        default: src = Wo; dst = g_Wof;  n4 = (DM * DM) / 4; break;
    }
    int i = blockIdx.x * blockDim.x + threadIdx.x;
    int stride = gridDim.x * blockDim.x;
    for (; i < n4; i += stride) {
        float4 v = ((const float4*)src)[i];
        ((__half2*)dst)[2 * i]     = __floats2half2_rn(v.x, v.y);
        ((__half2*)dst)[2 * i + 1] = __floats2half2_rn(v.z, v.w);
    }
}

// ---------------------------------------------------------------------------
// Kernel 1: QKV projections. 4-stage ring, prefetch distance 2 -> ONE sync/iter.
// smem per stage (halfs): X[128][40] @0 (5120), W[32][136] @5120 (4352).
// ---------------------------------------------------------------------------
#define P_W   5120
#define P_STAGE_B 18944

__global__ __launch_bounds__(256, 2) void proj_kernel(
    const float* __restrict__ bq, const float* __restrict__ bk, const float* __restrict__ bv)
{
    extern __shared__ __half sdyn[];
    __shared__ float sBias[128];

    int z = blockIdx.z;
    const float* bias = (z == 0) ? bq : (z == 1) ? bk : bv;
    __half* out = (z == 0) ? g_Qh : (z == 1) ? g_Kh : g_Vh;
    float oscale = (z == 0) ? 0.125f : 1.0f;

    int y = blockIdx.y;
    int b = y >> 3, h0 = (y & 7) * 2;
    int t0 = blockIdx.x * 128;

    const __half* Xp = g_Xf[z] + ((size_t)b * TKN + t0) * DM;
    const __half* Wp = g_Wf[z] + (size_t)h0 * DM * DK;

    int tid = threadIdx.x;
    int lane = tid & 31, w = tid >> 5;
    int wm = w & 3, wn = w >> 2;
    int g = lane >> 2, tg = lane & 3;

    if (tid < 128) sBias[tid] = bias[h0 * DK + tid];

    uint32_t sb0 = cvta_s(sdyn);

    int xrow = tid >> 2, xseg = tid & 3;
    int wrow_c = tid >> 4, wcol_c = (tid & 15) * 8;
    size_t wso = (size_t)(wcol_c >= 64 ? DM * DK : 0) + (size_t)wrow_c * DK + (wcol_c & 63);

    float acc[2][8][4];
#pragma unroll
    for (int mt = 0; mt < 2; mt++)
#pragma unroll
        for (int nt = 0; nt < 8; nt++)
#pragma unroll
            for (int q = 0; q < 4; q++) acc[mt][nt][q] = 0.0f;

    int arow = wm * 32 + ((lane >> 3) & 1) * 8 + (lane & 7);
    int acol = (lane >> 4) * 8;
    uint32_t a_off = (uint32_t)(arow * 40 + acol) * 2;
    uint32_t w_off = ((uint32_t)((lane >> 3) * 8 + (lane & 7)) * 136) * 2;

    auto stage = [&](int s, int d0) {
        uint32_t base = sb0 + s * P_STAGE_B;
#pragma unroll
        for (int i = 0; i < 2; i++) {
            int r = xrow + i * 64;
            cp16(base + (uint32_t)(r * 40 + xseg * 8) * 2,
                 Xp + (size_t)r * DM + d0 + xseg * 8);
        }
#pragma unroll
        for (int i = 0; i < 2; i++) {
            int r = wrow_c + i * 16;
            cp16(base + P_W * 2 + (uint32_t)(r * 136 + wcol_c) * 2,
                 Wp + wso + (size_t)(d0 + i * 16) * DK);
        }
        cpcommit();
    };

    stage(0, 0); stage(1, 32);

    const int nIter = DM / 32;
    for (int it = 0; it < nIter; it++) {
        // distance-2 prefetch into a 4-slot ring: (it+2)&3 never collides with
        // the slot slow readers may still hold ((it-1)&3) -> single sync/iter.
        if (it + 2 < nIter) { stage((it + 2) & 3, (it + 2) * 32); cpwait<2>(); }
        else if (it + 1 < nIter) cpwait<1>();
        else cpwait<0>();
        __syncthreads();

        uint32_t base = sb0 + (it & 3) * P_STAGE_B;
        uint32_t abh = base + a_off;
        uint32_t wbh = base + P_W * 2 + w_off;

        uint32_t AH[2][2][4];
#pragma unroll
        for (int mt = 0; mt < 2; mt++)
#pragma unroll
            for (int ks = 0; ks < 2; ks++)
                ldm4(AH[mt][ks], abh + (mt * 16 * 40 + ks * 16) * 2);

#pragma unroll
        for (int grp = 0; grp < 2; grp++) {
            uint32_t BH[4][4];
#pragma unroll
            for (int n4i = 0; n4i < 4; n4i++)
                ldm4t(BH[n4i], wbh + (wn * 64 + (grp * 4 + n4i) * 8) * 2);
#pragma unroll
            for (int ks = 0; ks < 2; ks++)
#pragma unroll
                for (int n4i = 0; n4i < 4; n4i++)
#pragma unroll
                    for (int mt = 0; mt < 2; mt++)
                        mmah(acc[mt][grp * 4 + n4i],
                             AH[mt][ks][0], AH[mt][ks][1], AH[mt][ks][2], AH[mt][ks][3],
                             BH[n4i][2 * ks], BH[n4i][2 * ks + 1]);
        }
    }

    __half* outh = out + ((size_t)(b * HEADS + h0 + wn) * TKN + t0) * DK;
#pragma unroll
    for (int mt = 0; mt < 2; mt++) {
        int r0 = wm * 32 + mt * 16 + g;
#pragma unroll
        for (int nt = 0; nt < 8; nt++) {
            int cl = nt * 8 + 2 * tg;
            float b0v = sBias[wn * 64 + cl], b1v = sBias[wn * 64 + cl + 1];
            *(__half2*)(outh + (size_t)r0 * DK + cl) =
                __floats2half2_rn((acc[mt][nt][0] + b0v) * oscale, (acc[mt][nt][1] + b1v) * oscale);
            *(__half2*)(outh + (size_t)(r0 + 8) * DK + cl) =
                __floats2half2_rn((acc[mt][nt][2] + b0v) * oscale, (acc[mt][nt][3] + b1v) * oscale);
        }
    }
}

// ---------------------------------------------------------------------------
// Kernel 2: flash attention; 128 queries / 8 warps / CTA.
// 3-slot K/V ring (distance 1 -> single sync/chunk); slot 2 reuses Q's smem
// (Q is register-resident after the prologue). smem total unchanged: 55296 B.
// Layout (bytes): Q @0 (18432); KV slot s base = ((s+1)%3)*18432;
// within a slot: K @ +0 (9216), V @ +9216.
// ---------------------------------------------------------------------------
__global__ __launch_bounds__(256) void flash_kernel()
{
    __shared__ __half smf[27648];   // 55296 B

    const float C = 1.4426950408889634f;

    int bh = blockIdx.y;
    int t0 = blockIdx.x * 128;
    const __half* Qp = g_Qh + (size_t)bh * TKN * DK;
    const __half* Kp = g_Kh + (size_t)bh * TKN * DK;
    const __half* Vp = g_Vh + (size_t)bh * TKN * DK;

    int tid = threadIdx.x;
    int lane = tid & 31, w = tid >> 5;
    int wq = w >> 2, wi = w & 3;
    int g = lane >> 2, tg = lane & 3;

    uint32_t sm0 = cvta_s(smf);

    auto stagekv = [&](int s, int s0) {
        uint32_t base = sm0 + (uint32_t)(((s + 1) % 3) * 18432);
#pragma unroll
        for (int i = 0; i < 2; i++) {
            int idx = i * 256 + tid;
            int r = idx >> 3, c = idx & 7;
            uint32_t dof = (uint32_t)(r * 72 + c * 8) * 2;
            cp16(base + dof,        Kp + (size_t)(s0 + r) * DK + c * 8);
            cp16(base + 9216 + dof, Vp + (size_t)(s0 + r) * DK + c * 8);
        }
        cpcommit();
    };

    stagekv(0, 0);

    // stage Q into slot-2 region (plain stores; freed after fragment extraction)
#pragma unroll
    for (int i = 0; i < 4; i++) {
        int idx = i * 256 + tid;
        int r = idx >> 3, c = idx & 7;
        *(uint4*)&smf[r * 72 + c * 8] = *(const uint4*)(Qp + (size_t)(t0 + r) * DK + c * 8);
    }
    __syncthreads();

    uint32_t Qa[4][4];
    {
        int qrow = wq * 64 + wi * 16 + ((lane >> 3) & 1) * 8 + (lane & 7);
        int qcol = (lane >> 4) * 8;
        uint32_t qbase = sm0 + (uint32_t)(qrow * 72 + qcol) * 2;
#pragma unroll
        for (int ks = 0; ks < 4; ks++) ldm4(Qa[ks], qbase + ks * 32);
    }

    uint32_t k_off = (((lane & 7) * 72 + (lane >> 3) * 8) << 1);
    uint32_t v_off = 9216 + ((((lane >> 3) * 8 + (lane & 7)) * 72) << 1);

    float m0 = -1e30f, m1 = -1e30f, l0 = 0.0f, l1 = 0.0f;
    float O[8][4];
#pragma unroll
    for (int nt = 0; nt < 8; nt++)
#pragma unroll
        for (int q = 0; q < 4; q++) O[nt][q] = 0.0f;

    const int nCh = TKN / 64;
    for (int it = 0; it < nCh; it++) {
        if (it + 1 < nCh) { stagekv((it + 1) % 3, (it + 1) * 64); cpwait<1>(); }
        else              { cpwait<0>(); }
        __syncthreads();

        uint32_t slot = sm0 + (uint32_t)(((it % 3) + 1) % 3 * 18432);
        uint32_t kbase = slot + k_off;
        uint32_t vbase = slot + v_off;

        float S[8][4];
#pragma unroll
        for (int nt = 0; nt < 8; nt++) {
#pragma unroll
            for (int q = 0; q < 4; q++) S[nt][q] = 0.0f;
            uint32_t bk[8];
            uint32_t ka = kbase + ((nt * 8 * 72) << 1);
            ldm4(bk,     ka);
            ldm4(bk + 4, ka + 64);
#pragma unroll
            for (int ks = 0; ks < 4; ks++)
                mmah(S[nt], Qa[ks][0], Qa[ks][1], Qa[ks][2], Qa[ks][3],
                     bk[2 * ks], bk[2 * ks + 1]);
        }

        float mx0 = fmaxf(S[0][0], S[0][1]);
        float mx1 = fmaxf(S[0][2], S[0][3]);
#pragma unroll
        for (int nt = 1; nt < 8; nt++) {
            mx0 = fmaxf(mx0, fmaxf(S[nt][0], S[nt][1]));
            mx1 = fmaxf(mx1, fmaxf(S[nt][2], S[nt][3]));
        }
        mx0 = fmaxf(mx0, __shfl_xor_sync(0xffffffffu, mx0, 1));
        mx0 = fmaxf(mx0, __shfl_xor_sync(0xffffffffu, mx0, 2));
        mx1 = fmaxf(mx1, __shfl_xor_sync(0xffffffffu, mx1, 1));
        mx1 = fmaxf(mx1, __shfl_xor_sync(0xffffffffu, mx1, 2));

        float mn0 = fmaxf(m0, mx0), mn1 = fmaxf(m1, mx1);
        float corr0 = ex2f((m0 - mn0) * C);
        float corr1 = ex2f((m1 - mn1) * C);
        m0 = mn0; m1 = mn1;
        float mc0 = mn0 * C, mc1 = mn1 * C;

        uint32_t P01[8], P23[8];
#pragma unroll
        for (int nt = 0; nt < 8; nt++) {
            P01[nt] = ex2h2(cvt2h(fmaf(S[nt][1], C, -mc0), fmaf(S[nt][0], C, -mc0)));
            P23[nt] = ex2h2(cvt2h(fmaf(S[nt][3], C, -mc1), fmaf(S[nt][2], C, -mc1)));
        }

        uint32_t s01 = hadd2u(hadd2u(hadd2u(P01[0], P01[1]), hadd2u(P01[2], P01[3])),
                              hadd2u(hadd2u(P01[4], P01[5]), hadd2u(P01[6], P01[7])));
        uint32_t s23 = hadd2u(hadd2u(hadd2u(P23[0], P23[1]), hadd2u(P23[2], P23[3])),
                              hadd2u(hadd2u(P23[4], P23[5]), hadd2u(P23[6], P23[7])));
        float rs0 = h2sumf(s01), rs1 = h2sumf(s23);
        rs0 += __shfl_xor_sync(0xffffffffu, rs0, 1);
        rs0 += __shfl_xor_sync(0xffffffffu, rs0, 2);
        rs1 += __shfl_xor_sync(0xffffffffu, rs1, 1);
        rs1 += __shfl_xor_sync(0xffffffffu, rs1, 2);
        l0 = l0 * corr0 + rs0;
        l1 = l1 * corr1 + rs1;

#pragma unroll
        for (int nt = 0; nt < 8; nt++) {
            O[nt][0] *= corr0; O[nt][1] *= corr0;
            O[nt][2] *= corr1; O[nt][3] *= corr1;
        }

#pragma unroll
        for (int nt = 0; nt < 8; nt++) {
            uint32_t bv[8];
            uint32_t va = vbase + ((nt * 8) << 1);
            ldm4t(bv,     va);
            ldm4t(bv + 4, va + ((32 * 72) << 1));
#pragma unroll
            for (int ks = 0; ks < 4; ks++)
                mmah(O[nt], P01[2 * ks], P23[2 * ks], P01[2 * ks + 1], P23[2 * ks + 1],
                     bv[2 * ks], bv[2 * ks + 1]);
        }
    }

    float inv0 = 1.0f / l0, inv1 = 1.0f / l1;
    size_t cb = (size_t)bh * TKN * DK;
    int r0 = t0 + wq * 64 + wi * 16 + g;
#pragma unroll
    for (int nt = 0; nt < 8; nt++) {
        int col = nt * 8 + 2 * tg;
        *(__half2*)(g_ctxh + cb + (size_t)r0 * DK + col) =
            __floats2half2_rn(O[nt][0] * inv0, O[nt][1] * inv0);
        *(__half2*)(g_ctxh + cb + (size_t)(r0 + 8) * DK + col) =
            __floats2half2_rn(O[nt][2] * inv1, O[nt][3] * inv1);
    }
}

// ---------------------------------------------------------------------------
// Kernel 3: output projection. 4-stage ring, distance 2 -> ONE sync/iter.
// smem per stage (halfs): A[128][40] @0, B[128][40] @5120. Stage = 20480 B.
// ---------------------------------------------------------------------------
#define O_BH 5120
#define O_STAGE_B 20480

__global__ __launch_bounds__(256, 2) void outproj_kernel(
    const float* __restrict__ bo, float* __restrict__ out)
{
    extern __shared__ __half sdyn[];
    __shared__ float sBias[128];

    int j0 = blockIdx.x * 128;
    int m0 = blockIdx.y * 128;

    int tid = threadIdx.x;
    int lane = tid & 31, w = tid >> 5;
    int wm = w & 3, wn = w >> 2;
    int g = lane >> 2, tg = lane & 3;

    if (tid < 128) sBias[tid] = bo[j0 + tid];

    uint32_t sb0 = cvta_s(sdyn);
    int xrow = tid >> 2, xseg = tid & 3;

    float acc[2][8][4];
#pragma unroll
    for (int mt = 0; mt < 2; mt++)
#pragma unroll
        for (int nt = 0; nt < 8; nt++)
#pragma unroll
            for (int q = 0; q < 4; q++) acc[mt][nt][q] = 0.0f;

    int arow = wm * 32 + ((lane >> 3) & 1) * 8 + (lane & 7);
    int acol = (lane >> 4) * 8;
    uint32_t a_off = (uint32_t)(arow * 40 + acol) * 2;
    uint32_t k_off = (uint32_t)((lane & 7) * 40 + (lane >> 3) * 8) * 2;

    auto stage = [&](int s, int d0) {
        uint32_t base = sb0 + s * O_STAGE_B;
#pragma unroll
        for (int i = 0; i < 2; i++) {
            int r = xrow + i * 64;
            uint32_t dof = (uint32_t)(r * 40 + xseg * 8) * 2;
            cp16(base + dof,            g_ctxh + (size_t)(m0 + r) * DM + d0 + xseg * 8);
            cp16(base + O_BH * 2 + dof, g_Wof  + (size_t)(j0 + r) * DM + d0 + xseg * 8);
        }
        cpcommit();
    };

    stage(0, 0); stage(1, 32);

    const int nIter = DM / 32;
    for (int it = 0; it < nIter; it++) {
        if (it + 2 < nIter) { stage((it + 2) & 3, (it + 2) * 32); cpwait<2>(); }
        else if (it + 1 < nIter) cpwait<1>();
        else cpwait<0>();
        __syncthreads();

        uint32_t base = sb0 + (it & 3) * O_STAGE_B;
        uint32_t abh = base + a_off;
        uint32_t kbh = base + O_BH * 2 + k_off;

        uint32_t AH[2][2][4];
#pragma unroll
        for (int mt = 0; mt < 2; mt++)
#pragma unroll
            for (int ks = 0; ks < 2; ks++)
                ldm4(AH[mt][ks], abh + (mt * 16 * 40 + ks * 16) * 2);

#pragma unroll
        for (int grp = 0; grp < 2; grp++) {
            uint32_t BH[4][4];
#pragma unroll
            for (int n4i = 0; n4i < 4; n4i++)
                ldm4(BH[n4i], kbh + ((wn * 64 + (grp * 4 + n4i) * 8) * 40) * 2);
#pragma unroll
            for (int ks = 0; ks < 2; ks++)
#pragma unroll
                for (int n4i = 0; n4i < 4; n4i++)
#pragma unroll
                    for (int mt = 0; mt < 2; mt++)
                        mmah(acc[mt][grp * 4 + n4i],
                             AH[mt][ks][0], AH[mt][ks][1], AH[mt][ks][2], AH[mt][ks][3],
                             BH[n4i][2 * ks], BH[n4i][2 * ks + 1]);
        }
    }

#pragma unroll
    for (int mt = 0; mt < 2; mt++) {
        int r0 = m0 + wm * 32 + mt * 16 + g;
#pragma unroll
        for (int nt = 0; nt < 8; nt++) {
            int cl = wn * 64 + nt * 8 + 2 * tg;
            float b0v = sBias[cl], b1v = sBias[cl + 1];
            *(float2*)(out + (size_t)r0 * DM + j0 + cl) =
                make_float2(acc[mt][nt][0] + b0v, acc[mt][nt][1] + b1v);
            *(float2*)(out + (size_t)(r0 + 8) * DM + j0 + cl) =
                make_float2(acc[mt][nt][2] + b0v, acc[mt][nt][3] + b1v);
        }
    }
}

// ---------------------------------------------------------------------------
extern "C" void kernel_launch(void* const* d_in, const int* in_sizes, int n_in,
                              void* d_out, int out_size)
{
    const float* Q  = (const float*)d_in[0];
    const float* K  = (const float*)d_in[1];
    const float* V  = (const float*)d_in[2];
    const float* Wq = (const float*)d_in[3];
    const float* bq = (const float*)d_in[4];
    const float* Wk = (const float*)d_in[5];
    const float* bk = (const float*)d_in[6];
    const float* Wv = (const float*)d_in[7];
    const float* bv = (const float*)d_in[8];
    const float* Wo = (const float*)d_in[9];
    const float* bo = (const float*)d_in[10];
    float* out = (float*)d_out;

    cudaFuncSetAttribute(proj_kernel, cudaFuncAttributeMaxDynamicSharedMemorySize, 4 * P_STAGE_B);
    cudaFuncSetAttribute(outproj_kernel, cudaFuncAttributeMaxDynamicSharedMemorySize, 4 * O_STAGE_B);

    dim3 gs(128, 7);
    split_kernel<<<gs, 256>>>(Q, K, V, Wq, Wk, Wv, Wo);

    dim3 g1(TKN / 128, B_SZ * 8, 3);
    proj_kernel<<<g1, 256, 4 * P_STAGE_B>>>(bq, bk, bv);

    dim3 g2(TKN / 128, B_SZ * HEADS);
    flash_kernel<<<g2, 256>>>();

    dim3 g3(DM / 128, (B_SZ * TKN) / 128);
    outproj_kernel<<<g3, 256, 4 * O_STAGE_B>>>(bo, out);
}